// round 4
// baseline (speedup 1.0000x reference)
#include <cuda_runtime.h>
#include <cstdint>
#include <cstddef>

#define NBATCH 8
#define CFEAT  256
#define NGROUP 8
#define CPG    32
#define NTOT   21760
#define KTOP   100
#define NLEV   4
#define GNEPS  1e-5f
#define NCB    170
#define NSEG   680          // 21760 / 32

// ---------------- device scratch ----------------
__device__ float   g_h[(size_t)NBATCH * CFEAT * NTOT];
__device__ float   g_logits[NBATCH * NTOT];
__device__ double2 g_part1[NLEV * NBATCH * NGROUP * 8];
__device__ double2 g_part2[NBATCH * NGROUP * NCB];
__device__ float   g_a1[NLEV * NBATCH * CFEAT];
__device__ float   g_d1[NLEV * NBATCH * CFEAT];
__device__ float   g_a2[NLEV * NBATCH * CFEAT];
__device__ float   g_d2[NLEV * NBATCH * CFEAT];

// ---------------- packed f32x2 helpers ----------------
__device__ __forceinline__ void ffma2(unsigned long long& d, unsigned long long a,
                                      unsigned long long b) {
    asm("fma.rn.f32x2 %0, %1, %2, %0;" : "+l"(d) : "l"(a), "l"(b));
}
__device__ __forceinline__ float2 unpack2(unsigned long long v) {
    float2 r;
    asm("mov.b64 {%0,%1}, %2;" : "=f"(r.x), "=f"(r.y) : "l"(v));
    return r;
}
__device__ __forceinline__ unsigned long long swap2(unsigned long long v) {
    unsigned long long r;
    asm("{ .reg .b32 lo, hi;\n\t mov.b64 {lo,hi}, %1;\n\t mov.b64 %0, {hi,lo}; }"
        : "=l"(r) : "l"(v));
    return r;
}

// ---------------- GN1 stats: single merged launch, all levels ----------------
__global__ __launch_bounds__(256)
void stats_all_kernel(const float* __restrict__ x0, const float* __restrict__ x1,
                      const float* __restrict__ x2, const float* __restrict__ x3,
                      double2* __restrict__ part1)
{
    // block table: lev0: 512 blocks (nch=8), lev1: 128 (nch=2), lev2: 64, lev3: 64
    int bi = blockIdx.x;
    int lev, nchLog, L;
    const float* src;
    if (bi < 512)      { lev = 0; nchLog = 3; L = 16384; src = x0; }
    else if (bi < 640) { lev = 1; nchLog = 1; L = 4096;  src = x1; bi -= 512; }
    else if (bi < 704) { lev = 2; nchLog = 0; L = 1024;  src = x2; bi -= 640; }
    else               { lev = 3; nchLog = 0; L = 256;   src = x3; bi -= 704; }
    const int nch = 1 << nchLog;
    const int ch = bi & (nch - 1);
    const int bg = bi >> nchLog;
    const int b = bg >> 3, g = bg & 7;
    const int chunk = L >> nchLog;
    const int q0 = (ch * chunk) >> 2;
    const int q1 = ((ch + 1) * chunk) >> 2;
    const int tid = threadIdx.x;

    float s = 0.f, q = 0.f;
    for (int c = 0; c < CPG; ++c) {
        const float4* row = (const float4*)(src + (size_t)(b * CFEAT + g * CPG + c) * L);
        for (int i = q0 + tid; i < q1; i += 256) {
            float4 v = row[i];
            s += (v.x + v.y) + (v.z + v.w);
            q += (v.x * v.x + v.y * v.y) + (v.z * v.z + v.w * v.w);
        }
    }
#pragma unroll
    for (int off = 16; off; off >>= 1) {
        s += __shfl_down_sync(0xffffffffu, s, off);
        q += __shfl_down_sync(0xffffffffu, q, off);
    }
    __shared__ float ws[8], wq[8];
    if ((tid & 31) == 0) { ws[tid >> 5] = s; wq[tid >> 5] = q; }
    __syncthreads();
    if (tid == 0) {
        double S = 0.0, Q = 0.0;
        for (int w = 0; w < 8; ++w) { S += (double)ws[w]; Q += (double)wq[w]; }
        part1[lev * 512 + (b * NGROUP + g) * 8 + ch] = make_double2(S, Q);
    }
}

__global__ void finalize1_kernel(const double2* __restrict__ part,
                                 const float* __restrict__ scale, const float* __restrict__ bias,
                                 float* __restrict__ aOut, float* __restrict__ dOut)
{
    const int idx = blockIdx.x;                 // lev*64 + b*8 + g
    const int lev = idx >> 6, b = (idx >> 3) & 7, g = idx & 7;
    const int nchs[4] = {8, 2, 1, 1};
    const int Ls[4] = {16384, 4096, 1024, 256};
    const int nch = nchs[lev];

    double s = 0.0, ss = 0.0;
    for (int ch = 0; ch < nch; ++ch) {
        double2 p = part[lev * 512 + (b * NGROUP + g) * 8 + ch];
        s += p.x; ss += p.y;
    }
    const double cnt = 32.0 * (double)Ls[lev];
    const double mu = s / cnt;
    const float var = (float)(ss / cnt - mu * mu);
    const float rinv = rsqrtf(var + GNEPS);

    const int c = g * CPG + threadIdx.x;
    const float a = scale[c] * rinv;
    aOut[(lev * NBATCH + b) * CFEAT + c] = a;
    dOut[(lev * NBATCH + b) * CFEAT + c] = bias[c] - (float)mu * a;
}

// ---------------- stage 2: fused GN1+ReLU + FFMA2 GEMM (swap trick) + bias + GN2 stats ----------------
__global__ __launch_bounds__(256, 2)
void gemm1_kernel(const float* __restrict__ x, const float* __restrict__ W1,
                  const float* __restrict__ b1,
                  const float* __restrict__ a1, const float* __restrict__ d1,
                  float* __restrict__ hbase, double2* __restrict__ part2,
                  int L, int colOff, int colBase)
{
    __shared__ float As[2][8][128];
    __shared__ float Bs[2][8][128];
    __shared__ float sa[256], sd[256];
    __shared__ float redS[8], redQ[8];

    const int tid = threadIdx.x;
    const int b   = blockIdx.z;
    const int om2 = blockIdx.y;
    const int om  = om2 * 128;
    const int ln  = blockIdx.x * 128;

    sa[tid] = a1[b * 256 + tid];
    sd[tid] = d1[b * 256 + tid];

    const float* xb = x + (size_t)b * 256 * L;

    const int am = tid >> 1;
    const int ak = (tid & 1) * 4;
    const int bk = tid >> 5;
    const int bn = (tid & 31) * 4;
    const int ty = tid >> 4;
    const int tx = tid & 15;

    // acc0[mp][np] = (m0*n0, m1*n1); acc1[mp][np] = (m0*n1, m1*n0)
    unsigned long long acc0[4][4], acc1[4][4];
#pragma unroll
    for (int i = 0; i < 4; ++i)
#pragma unroll
        for (int j = 0; j < 4; ++j) { acc0[i][j] = 0ull; acc1[i][j] = 0ull; }

    __syncthreads();

    {
        float4 w = *(const float4*)&W1[(om + am) * 256 + ak];
        float4 v = *(const float4*)&xb[(size_t)bk * L + ln + bn];
        float a = sa[bk], d = sd[bk];
        As[0][ak + 0][am] = w.x; As[0][ak + 1][am] = w.y;
        As[0][ak + 2][am] = w.z; As[0][ak + 3][am] = w.w;
        float4 t = make_float4(fmaxf(fmaf(a, v.x, d), 0.f), fmaxf(fmaf(a, v.y, d), 0.f),
                               fmaxf(fmaf(a, v.z, d), 0.f), fmaxf(fmaf(a, v.w, d), 0.f));
        *(float4*)&Bs[0][bk][bn] = t;
    }
    __syncthreads();

    for (int kt = 0; kt < 32; ++kt) {
        const int cur = kt & 1;
        float4 wn, vn; float an = 0.f, dn = 0.f;
        if (kt < 31) {
            const int kc = (kt + 1) * 8;
            wn = *(const float4*)&W1[(om + am) * 256 + kc + ak];
            vn = *(const float4*)&xb[(size_t)(kc + bk) * L + ln + bn];
            an = sa[kc + bk]; dn = sd[kc + bk];
        }
#pragma unroll
        for (int kk = 0; kk < 8; ++kk) {
            ulonglong2 aA = *reinterpret_cast<const ulonglong2*>(&As[cur][kk][ty * 8]);
            ulonglong2 aB = *reinterpret_cast<const ulonglong2*>(&As[cur][kk][ty * 8 + 4]);
            ulonglong2 bA = *reinterpret_cast<const ulonglong2*>(&Bs[cur][kk][tx * 8]);
            ulonglong2 bB = *reinterpret_cast<const ulonglong2*>(&Bs[cur][kk][tx * 8 + 4]);
            unsigned long long av[4] = {aA.x, aA.y, aB.x, aB.y};
            unsigned long long bv[4] = {bA.x, bA.y, bB.x, bB.y};
            unsigned long long bs[4];
#pragma unroll
            for (int j = 0; j < 4; ++j) bs[j] = swap2(bv[j]);
#pragma unroll
            for (int mp = 0; mp < 4; ++mp)
#pragma unroll
                for (int np = 0; np < 4; ++np) {
                    ffma2(acc0[mp][np], av[mp], bv[np]);
                    ffma2(acc1[mp][np], av[mp], bs[np]);
                }
        }
        if (kt < 31) {
            const int nxt = cur ^ 1;
            As[nxt][ak + 0][am] = wn.x; As[nxt][ak + 1][am] = wn.y;
            As[nxt][ak + 2][am] = wn.z; As[nxt][ak + 3][am] = wn.w;
            float4 t = make_float4(fmaxf(fmaf(an, vn.x, dn), 0.f), fmaxf(fmaf(an, vn.y, dn), 0.f),
                                   fmaxf(fmaf(an, vn.z, dn), 0.f), fmaxf(fmaf(an, vn.w, dn), 0.f));
            *(float4*)&Bs[nxt][bk][bn] = t;
        }
        __syncthreads();
    }

    // epilogue: +bias, unscramble pairs, write h, per-thread group stats
    float* hrow = hbase + ((size_t)(b * 256 + om)) * NTOT + colOff + ln;
    float s = 0.f, q = 0.f;
#pragma unroll
    for (int mp = 0; mp < 4; ++mp) {
        const int r0 = ty * 8 + 2 * mp, r1 = r0 + 1;
        const float bb0 = b1[om + r0], bb1 = b1[om + r1];
        float2 c0[4], c1[4];
#pragma unroll
        for (int np = 0; np < 4; ++np) { c0[np] = unpack2(acc0[mp][np]); c1[np] = unpack2(acc1[mp][np]); }
        float v0[8] = {c0[0].x + bb0, c1[0].x + bb0, c0[1].x + bb0, c1[1].x + bb0,
                       c0[2].x + bb0, c1[2].x + bb0, c0[3].x + bb0, c1[3].x + bb0};
        float v1[8] = {c1[0].y + bb1, c0[0].y + bb1, c1[1].y + bb1, c0[1].y + bb1,
                       c1[2].y + bb1, c0[2].y + bb1, c1[3].y + bb1, c0[3].y + bb1};
        *(float4*)&hrow[(size_t)r0 * NTOT + tx * 8]     = make_float4(v0[0], v0[1], v0[2], v0[3]);
        *(float4*)&hrow[(size_t)r0 * NTOT + tx * 8 + 4] = make_float4(v0[4], v0[5], v0[6], v0[7]);
        *(float4*)&hrow[(size_t)r1 * NTOT + tx * 8]     = make_float4(v1[0], v1[1], v1[2], v1[3]);
        *(float4*)&hrow[(size_t)r1 * NTOT + tx * 8 + 4] = make_float4(v1[4], v1[5], v1[6], v1[7]);
#pragma unroll
        for (int j = 0; j < 8; ++j) {
            s += v0[j] + v1[j];
            q += v0[j] * v0[j] + v1[j] * v1[j];
        }
    }
    // all 8 rows of a thread lie in group (ty>>2); constant within a warp
#pragma unroll
    for (int off = 16; off; off >>= 1) {
        s += __shfl_down_sync(0xffffffffu, s, off);
        q += __shfl_down_sync(0xffffffffu, q, off);
    }
    const int wid = tid >> 5;
    if ((tid & 31) == 0) { redS[wid] = s; redQ[wid] = q; }
    __syncthreads();
    if (tid < 4) {
        const int cb = colBase + blockIdx.x;
        const int g = om2 * 4 + tid;
        const double S = (double)redS[2 * tid] + (double)redS[2 * tid + 1];
        const double Q = (double)redQ[2 * tid] + (double)redQ[2 * tid + 1];
        part2[(size_t)(b * NGROUP + g) * NCB + cb] = make_double2(S, Q);
    }
}

// ---------------- finalize GN2 ----------------
__global__ void finalize2_kernel(const double2* __restrict__ part2,
                                 const float* __restrict__ scale, const float* __restrict__ bias,
                                 float* __restrict__ aOut, float* __restrict__ dOut)
{
    const int idx = blockIdx.x;
    const int lev = idx >> 6, b = (idx >> 3) & 7, g = idx & 7;
    const int cbS[5] = {0, 128, 160, 168, 170};
    const int Ls[4] = {16384, 4096, 1024, 256};

    double s = 0.0, ss = 0.0;
    for (int cb = cbS[lev]; cb < cbS[lev + 1]; ++cb) {
        double2 p = part2[(size_t)(b * NGROUP + g) * NCB + cb];
        s += p.x; ss += p.y;
    }
    const double cnt = 32.0 * (double)Ls[lev];
    const double mu = s / cnt;
    const float var = (float)(ss / cnt - mu * mu);
    const float rinv = rsqrtf(var + GNEPS);

    const int c = g * CPG + threadIdx.x;
    const float a = scale[c] * rinv;
    aOut[(lev * NBATCH + b) * CFEAT + c] = a;
    dOut[(lev * NBATCH + b) * CFEAT + c] = bias[c] - (float)mu * a;
}

// ---------------- stage 4: GN2-affine + ReLU + W2 dot + b2 -> logits (float4) ----------------
__global__ __launch_bounds__(256)
void logits_kernel(const float* __restrict__ h, const float* __restrict__ a2,
                   const float* __restrict__ d2, const float* __restrict__ W2,
                   const float* __restrict__ b2, float* __restrict__ logits,
                   float* __restrict__ outLog, int colOff, int L)
{
    __shared__ float sa[256], sd[256], sw[256];
    const int tid = threadIdx.x;
    const int b = blockIdx.y;
    sa[tid] = a2[b * 256 + tid];
    sd[tid] = d2[b * 256 + tid];
    sw[tid] = W2[tid];
    __syncthreads();

    const int rel = blockIdx.x * 1024 + tid * 4;
    if (rel >= L) return;
    const int pos = colOff + rel;
    const float* hp = h + (size_t)b * 256 * NTOT + pos;
    const float bb = b2[0];
    float4 acc = make_float4(bb, bb, bb, bb);
#pragma unroll 4
    for (int c = 0; c < 256; ++c) {
        float4 v = *(const float4*)&hp[(size_t)c * NTOT];
        const float w = sw[c], a = sa[c], d = sd[c];
        acc.x = fmaf(w, fmaxf(fmaf(a, v.x, d), 0.f), acc.x);
        acc.y = fmaf(w, fmaxf(fmaf(a, v.y, d), 0.f), acc.y);
        acc.z = fmaf(w, fmaxf(fmaf(a, v.z, d), 0.f), acc.z);
        acc.w = fmaf(w, fmaxf(fmaf(a, v.w, d), 0.f), acc.w);
    }
    *(float4*)&logits[b * NTOT + pos] = acc;
    if (outLog) *(float4*)&outLog[b * NTOT + pos] = acc;
}

// ---------------- stage 5: segmented top-100 ----------------
__device__ __forceinline__ unsigned ford(float f) {
    unsigned u = __float_as_uint(f);
    return (u & 0x80000000u) ? ~u : (u | 0x80000000u);
}

__global__ __launch_bounds__(1024)
void topk_kernel(const float* __restrict__ logits, float* __restrict__ outF, int* __restrict__ outI)
{
    extern __shared__ float sv[];                 // [NTOT] values, then [NSEG] segment maxima
    float* segMax = sv + NTOT;
    __shared__ unsigned long long warpRes[32];
    __shared__ int winSeg;
    const int b = blockIdx.x, tid = threadIdx.x;
    const int lane = tid & 31, wid = tid >> 5;
    const float NEGINF = __int_as_float(0xff800000);

    for (int i = tid; i < NTOT; i += 1024) sv[i] = logits[b * NTOT + i];
    __syncthreads();
    if (tid < NSEG) {
        float m = NEGINF;
        for (int j = 0; j < 32; ++j) m = fmaxf(m, sv[tid * 32 + j]);
        segMax[tid] = m;
    }
    __syncthreads();

    for (int k = 0; k < KTOP; ++k) {
        // global scan of segment maxima
        unsigned long long key = 0ull;
        if (tid < NSEG)
            key = ((unsigned long long)ford(segMax[tid]) << 32) | (unsigned)(NSEG - 1 - tid);
#pragma unroll
        for (int off = 16; off; off >>= 1) {
            unsigned long long o = __shfl_down_sync(0xffffffffu, key, off);
            key = (o > key) ? o : key;
        }
        if (lane == 0) warpRes[wid] = key;
        __syncthreads();
        if (wid == 0) {
            unsigned long long v = warpRes[lane];
#pragma unroll
            for (int off = 16; off; off >>= 1) {
                unsigned long long o = __shfl_down_sync(0xffffffffu, v, off);
                v = (o > v) ? o : v;
            }
            if (lane == 0) winSeg = NSEG - 1 - (int)(v & 0xffffffffu);
        }
        __syncthreads();
        // warp 0 resolves within the winning segment, emits, and repairs segMax
        if (wid == 0) {
            const int s = winSeg;
            float v = sv[s * 32 + lane];
            unsigned long long k2 = ((unsigned long long)ford(v) << 32) | (unsigned)(31 - lane);
            unsigned long long r = k2;
#pragma unroll
            for (int off = 16; off; off >>= 1) {
                unsigned long long o = __shfl_xor_sync(0xffffffffu, r, off);
                r = (o > r) ? o : r;
            }
            const int wl = 31 - (int)(r & 31u);
            if (lane == wl) {
                const int idx = s * 32 + wl;
                if (outF) outF[b * KTOP + k] = (float)idx;
                if (outI) outI[b * KTOP + k] = idx;
                sv[idx] = NEGINF;
                v = NEGINF;
            }
            float m = v;
#pragma unroll
            for (int off = 16; off; off >>= 1)
                m = fmaxf(m, __shfl_xor_sync(0xffffffffu, m, off));
            if (lane == 0) segMax[s] = m;
        }
        __syncthreads();
    }
}

// ---------------- host launcher ----------------
extern "C" void kernel_launch(void* const* d_in, const int* in_sizes, int n_in,
                              void* d_out, int out_size)
{
    (void)in_sizes; (void)n_in;
    const float* xs[4] = {(const float*)d_in[0], (const float*)d_in[1],
                          (const float*)d_in[2], (const float*)d_in[3]};
    const float* gn1_scale = (const float*)d_in[4];
    const float* gn1_bias  = (const float*)d_in[5];
    const float* W1        = (const float*)d_in[6];
    const float* b1        = (const float*)d_in[7];
    const float* gn2_scale = (const float*)d_in[8];
    const float* gn2_bias  = (const float*)d_in[9];
    const float* W2        = (const float*)d_in[10];
    const float* b2        = (const float*)d_in[11];

    const int Ls[4]   = {16384, 4096, 1024, 256};
    const int offs[4] = {0, 16384, 20480, 21504};

    void* tmp;
    cudaGetSymbolAddress(&tmp, g_h);      float*   p_h     = (float*)tmp;
    cudaGetSymbolAddress(&tmp, g_logits); float*   p_log   = (float*)tmp;
    cudaGetSymbolAddress(&tmp, g_part1);  double2* p_part1 = (double2*)tmp;
    cudaGetSymbolAddress(&tmp, g_part2);  double2* p_part2 = (double2*)tmp;
    cudaGetSymbolAddress(&tmp, g_a1);     float*   p_a1    = (float*)tmp;
    cudaGetSymbolAddress(&tmp, g_d1);     float*   p_d1    = (float*)tmp;
    cudaGetSymbolAddress(&tmp, g_a2);     float*   p_a2    = (float*)tmp;
    cudaGetSymbolAddress(&tmp, g_d2);     float*   p_d2    = (float*)tmp;

    float* outF   = (float*)d_out;
    float* outLog = nullptr;
    float* outIdF = nullptr;
    int*   outIdI = nullptr;
    const int NIDS = NBATCH * KTOP;
    const int NLOG = NBATCH * NTOT;
    if (out_size >= NIDS + NLOG)      { outIdF = outF; outLog = outF + NIDS; }
    else if (out_size == NLOG)        { outLog = outF; }
    else if (out_size == NIDS)        { outIdI = (int*)d_out; }
    else                              { outIdF = outF; if (out_size > NIDS) outLog = outF + NIDS; }

    // 1) GN1 stats (single launch, all levels)
    stats_all_kernel<<<768, 256>>>(xs[0], xs[1], xs[2], xs[3], p_part1);
    finalize1_kernel<<<NLEV * NBATCH * NGROUP, 32>>>(p_part1, gn1_scale, gn1_bias, p_a1, p_d1);

    // 2) fused GN1+ReLU+GEMM1 + bias + GN2 partial stats -> h
    for (int lev = 0; lev < 4; ++lev) {
        gemm1_kernel<<<dim3(Ls[lev] / 128, 2, NBATCH), 256>>>(
            xs[lev], W1, b1, p_a1 + lev * NBATCH * CFEAT, p_d1 + lev * NBATCH * CFEAT,
            p_h, p_part2, Ls[lev], offs[lev], offs[lev] / 128);
    }

    // 3) finalize GN2
    finalize2_kernel<<<NLEV * NBATCH * NGROUP, 32>>>(p_part2, gn2_scale, gn2_bias, p_a2, p_d2);

    // 4) logits
    for (int lev = 0; lev < 4; ++lev) {
        const int nblk = (Ls[lev] + 1023) / 1024;
        logits_kernel<<<dim3(nblk, NBATCH), 256>>>(
            p_h, p_a2 + lev * NBATCH * CFEAT, p_d2 + lev * NBATCH * CFEAT,
            W2, b2, p_log, outLog, offs[lev], Ls[lev]);
    }

    // 5) segmented top-k
    const int tkSmem = (NTOT + NSEG) * 4;
    cudaFuncSetAttribute(topk_kernel, cudaFuncAttributeMaxDynamicSharedMemorySize, tkSmem);
    topk_kernel<<<NBATCH, 1024, tkSmem>>>(p_log, outIdF, outIdI);
}

// round 7
// speedup vs baseline: 1.1517x; 1.1517x over previous
#include <cuda_runtime.h>
#include <cstdint>
#include <cstddef>

#define NBATCH 8
#define CFEAT  256
#define NGROUP 8
#define NTOT   21760
#define KTOP   100
#define GNEPS  1e-5f
#define NCB    170
#define NSEG   680
#define PADW   136

__device__ float   g_h[(size_t)NBATCH * CFEAT * NTOT];
__device__ float   g_logits[NBATCH * NTOT];
__device__ double2 g_part1[4 * NBATCH * NGROUP * 8];
__device__ double2 g_part2[NBATCH * NGROUP * NCB];
__device__ float   g_a1[4 * NBATCH * CFEAT];
__device__ float   g_d1[4 * NBATCH * CFEAT];
__device__ float   g_a2[4 * NBATCH * CFEAT];
__device__ float   g_d2[4 * NBATCH * CFEAT];

// tf32 round-to-nearest; result is exactly representable in fp32 (low 13 bits zero)
__device__ __forceinline__ float tf32f(float v) {
    uint32_t r;
    asm("cvt.rna.tf32.f32 %0, %1;" : "=r"(r) : "f"(v));
    return __uint_as_float(r);
}
__device__ __forceinline__ void mma_tf32(float* d, const float* a, float b0, float b1) {
    asm volatile(
        "mma.sync.aligned.m16n8k8.row.col.f32.tf32.tf32.f32 "
        "{%0,%1,%2,%3}, {%4,%5,%6,%7}, {%8,%9}, {%0,%1,%2,%3};"
        : "+f"(d[0]), "+f"(d[1]), "+f"(d[2]), "+f"(d[3])
        : "r"(__float_as_uint(a[0])), "r"(__float_as_uint(a[1])),
          "r"(__float_as_uint(a[2])), "r"(__float_as_uint(a[3])),
          "r"(__float_as_uint(b0)), "r"(__float_as_uint(b1)));
}

// ---------------- GN1 stats (merged) ----------------
__global__ __launch_bounds__(256)
void stats_all_kernel(const float* __restrict__ x0, const float* __restrict__ x1,
                      const float* __restrict__ x2, const float* __restrict__ x3,
                      double2* __restrict__ part1)
{
    int bi = blockIdx.x;
    int lev, nchLog, L;
    const float* src;
    if (bi < 512)      { lev = 0; nchLog = 3; L = 16384; src = x0; }
    else if (bi < 640) { lev = 1; nchLog = 1; L = 4096;  src = x1; bi -= 512; }
    else if (bi < 704) { lev = 2; nchLog = 0; L = 1024;  src = x2; bi -= 640; }
    else               { lev = 3; nchLog = 0; L = 256;   src = x3; bi -= 704; }
    const int nch = 1 << nchLog;
    const int ch = bi & (nch - 1);
    const int bg = bi >> nchLog;
    const int b = bg >> 3, g = bg & 7;
    const int chunk = L >> nchLog;
    const int q0 = (ch * chunk) >> 2, q1 = ((ch + 1) * chunk) >> 2;
    const int tid = threadIdx.x;

    float s = 0.f, q = 0.f;
    for (int c = 0; c < 32; ++c) {
        const float4* row = (const float4*)(src + (size_t)(b * CFEAT + g * 32 + c) * L);
        for (int i = q0 + tid; i < q1; i += 256) {
            float4 v = row[i];
            s += (v.x + v.y) + (v.z + v.w);
            q += (v.x * v.x + v.y * v.y) + (v.z * v.z + v.w * v.w);
        }
    }
#pragma unroll
    for (int off = 16; off; off >>= 1) {
        s += __shfl_down_sync(0xffffffffu, s, off);
        q += __shfl_down_sync(0xffffffffu, q, off);
    }
    __shared__ float ws[8], wq[8];
    if ((tid & 31) == 0) { ws[tid >> 5] = s; wq[tid >> 5] = q; }
    __syncthreads();
    if (tid == 0) {
        double S = 0.0, Q = 0.0;
        for (int w = 0; w < 8; ++w) { S += (double)ws[w]; Q += (double)wq[w]; }
        part1[lev * 512 + (b * NGROUP + g) * 8 + ch] = make_double2(S, Q);
    }
}

__global__ void finalize1_kernel(const double2* __restrict__ part,
                                 const float* __restrict__ scale, const float* __restrict__ bias,
                                 float* __restrict__ aOut, float* __restrict__ dOut)
{
    const int idx = blockIdx.x;
    const int lev = idx >> 6, b = (idx >> 3) & 7, g = idx & 7;
    const int nchs[4] = {8, 2, 1, 1};
    const int Ls[4] = {16384, 4096, 1024, 256};
    double s = 0.0, ss = 0.0;
    for (int ch = 0; ch < nchs[lev]; ++ch) {
        double2 p = part[lev * 512 + (b * NGROUP + g) * 8 + ch];
        s += p.x; ss += p.y;
    }
    const double cnt = 32.0 * (double)Ls[lev];
    const double mu = s / cnt;
    const float var = (float)(ss / cnt - mu * mu);
    const float rinv = rsqrtf(var + GNEPS);
    const int c = g * 32 + threadIdx.x;
    const float a = scale[c] * rinv;
    aOut[(lev * NBATCH + b) * CFEAT + c] = a;
    dOut[(lev * NBATCH + b) * CFEAT + c] = bias[c] - (float)mu * a;
}

// ---------------- mma.sync TF32x3 GEMM: GN1+ReLU in, bias + GN2 stats out ----------------
__global__ __launch_bounds__(256, 2)
void gemm_mma_kernel(const float* __restrict__ x, const float* __restrict__ W1,
                     const float* __restrict__ b1,
                     const float* __restrict__ a1, const float* __restrict__ d1,
                     float* __restrict__ hbase, double2* __restrict__ part2,
                     int L, int colOff, int colBase)
{
    __shared__ float Ah[2][8][PADW], Al[2][8][PADW];
    __shared__ float Bh[2][8][PADW], Bl[2][8][PADW];
    __shared__ float sa[256], sd[256];
    __shared__ float redS[8], redQ[8];

    const int tid = threadIdx.x;
    const int wid = tid >> 5, lane = tid & 31;
    const int b   = blockIdx.z;
    const int om2 = blockIdx.y;
    const int om  = om2 * 128;
    const int ln  = blockIdx.x * 128;

    sa[tid] = a1[b * 256 + tid];
    sd[tid] = d1[b * 256 + tid];

    const float* xb = x + (size_t)b * 256 * L;

    const int am = tid >> 1, ak = (tid & 1) * 4;     // A staging
    const int bk = tid >> 5, bn = (tid & 31) * 4;    // B staging

    const int wm = (wid & 3) * 32;     // warp m-offset
    const int wn = (wid >> 2) * 64;    // warp n-offset
    const int g = lane >> 2, c = lane & 3;

    float acc[2][8][4];
#pragma unroll
    for (int i = 0; i < 2; ++i)
#pragma unroll
        for (int j = 0; j < 8; ++j)
#pragma unroll
            for (int r = 0; r < 4; ++r) acc[i][j][r] = 0.f;

    __syncthreads();

    // preload k-step 0
    {
        float4 w = *(const float4*)&W1[(om + am) * 256 + ak];
        float wh[4] = {tf32f(w.x), tf32f(w.y), tf32f(w.z), tf32f(w.w)};
        Ah[0][ak + 0][am] = wh[0]; Ah[0][ak + 1][am] = wh[1];
        Ah[0][ak + 2][am] = wh[2]; Ah[0][ak + 3][am] = wh[3];
        Al[0][ak + 0][am] = tf32f(w.x - wh[0]); Al[0][ak + 1][am] = tf32f(w.y - wh[1]);
        Al[0][ak + 2][am] = tf32f(w.z - wh[2]); Al[0][ak + 3][am] = tf32f(w.w - wh[3]);
        float4 v = *(const float4*)&xb[(size_t)bk * L + ln + bn];
        float a = sa[bk], d = sd[bk];
        float t[4] = {fmaxf(fmaf(a, v.x, d), 0.f), fmaxf(fmaf(a, v.y, d), 0.f),
                      fmaxf(fmaf(a, v.z, d), 0.f), fmaxf(fmaf(a, v.w, d), 0.f)};
#pragma unroll
        for (int j2 = 0; j2 < 4; ++j2) {
            float hi = tf32f(t[j2]);
            Bh[0][bk][bn + j2] = hi;
            Bl[0][bk][bn + j2] = tf32f(t[j2] - hi);
        }
    }
    __syncthreads();

    for (int kt = 0; kt < 32; ++kt) {
        const int cur = kt & 1;
        float4 wn4, vn4; float an = 0.f, dn = 0.f;
        if (kt < 31) {
            const int kc = (kt + 1) * 8;
            wn4 = *(const float4*)&W1[(om + am) * 256 + kc + ak];
            vn4 = *(const float4*)&xb[(size_t)(kc + bk) * L + ln + bn];
            an = sa[kc + bk]; dn = sd[kc + bk];
        }
        // load A fragments (conflict-free: bank = c*8+g within 32)
        float ah[2][4], al[2][4];
#pragma unroll
        for (int i = 0; i < 2; ++i) {
            const int m0 = wm + i * 16;
            ah[i][0] = Ah[cur][c][m0 + g];     ah[i][1] = Ah[cur][c][m0 + g + 8];
            ah[i][2] = Ah[cur][c + 4][m0 + g]; ah[i][3] = Ah[cur][c + 4][m0 + g + 8];
            al[i][0] = Al[cur][c][m0 + g];     al[i][1] = Al[cur][c][m0 + g + 8];
            al[i][2] = Al[cur][c + 4][m0 + g]; al[i][3] = Al[cur][c + 4][m0 + g + 8];
        }
#pragma unroll
        for (int j = 0; j < 8; ++j) {
            const int n0 = wn + j * 8 + g;
            float bh0 = Bh[cur][c][n0], bh1 = Bh[cur][c + 4][n0];
            float bl0 = Bl[cur][c][n0], bl1 = Bl[cur][c + 4][n0];
#pragma unroll
            for (int i = 0; i < 2; ++i) {
                mma_tf32(acc[i][j], ah[i], bh0, bh1);
                mma_tf32(acc[i][j], ah[i], bl0, bl1);
                mma_tf32(acc[i][j], al[i], bh0, bh1);
            }
        }
        if (kt < 31) {
            const int nxt = cur ^ 1;
            float wh[4] = {tf32f(wn4.x), tf32f(wn4.y), tf32f(wn4.z), tf32f(wn4.w)};
            Ah[nxt][ak + 0][am] = wh[0]; Ah[nxt][ak + 1][am] = wh[1];
            Ah[nxt][ak + 2][am] = wh[2]; Ah[nxt][ak + 3][am] = wh[3];
            Al[nxt][ak + 0][am] = tf32f(wn4.x - wh[0]); Al[nxt][ak + 1][am] = tf32f(wn4.y - wh[1]);
            Al[nxt][ak + 2][am] = tf32f(wn4.z - wh[2]); Al[nxt][ak + 3][am] = tf32f(wn4.w - wh[3]);
            float t[4] = {fmaxf(fmaf(an, vn4.x, dn), 0.f), fmaxf(fmaf(an, vn4.y, dn), 0.f),
                          fmaxf(fmaf(an, vn4.z, dn), 0.f), fmaxf(fmaf(an, vn4.w, dn), 0.f)};
#pragma unroll
            for (int j2 = 0; j2 < 4; ++j2) {
                float hi = tf32f(t[j2]);
                Bh[nxt][bk][bn + j2] = hi;
                Bl[nxt][bk][bn + j2] = tf32f(t[j2] - hi);
            }
        }
        __syncthreads();
    }

    // epilogue: +bias, write h (float2 stores), fused GN2 partial stats
    float s = 0.f, q = 0.f;
#pragma unroll
    for (int i = 0; i < 2; ++i) {
        const int r0 = om + wm + i * 16 + g;
        const int r1 = r0 + 8;
        const float bb0 = b1[r0], bb1 = b1[r1];
        float* h0 = hbase + (size_t)(b * 256 + r0) * NTOT + colOff + ln;
        float* h1 = hbase + (size_t)(b * 256 + r1) * NTOT + colOff + ln;
#pragma unroll
        for (int j = 0; j < 8; ++j) {
            const int cn = wn + j * 8 + 2 * c;
            float v0 = acc[i][j][0] + bb0, v1 = acc[i][j][1] + bb0;
            float v2 = acc[i][j][2] + bb1, v3 = acc[i][j][3] + bb1;
            *(float2*)&h0[cn] = make_float2(v0, v1);
            *(float2*)&h1[cn] = make_float2(v2, v3);
            s += (v0 + v1) + (v2 + v3);
            q += v0 * v0 + v1 * v1 + v2 * v2 + v3 * v3;
        }
    }
#pragma unroll
    for (int off = 16; off; off >>= 1) {
        s += __shfl_down_sync(0xffffffffu, s, off);
        q += __shfl_down_sync(0xffffffffu, q, off);
    }
    if (lane == 0) { redS[wid] = s; redQ[wid] = q; }
    __syncthreads();
    if (tid < 4) {   // group = om2*4 + (wid&3); warps wid and wid+4 share a group
        const int grp = om2 * 4 + tid;
        const int cb = colBase + blockIdx.x;
        const double S = (double)redS[tid] + (double)redS[tid + 4];
        const double Q = (double)redQ[tid] + (double)redQ[tid + 4];
        part2[(size_t)(b * NGROUP + grp) * NCB + cb] = make_double2(S, Q);
    }
}

// ---------------- finalize GN2 ----------------
__global__ void finalize2_kernel(const double2* __restrict__ part2,
                                 const float* __restrict__ scale, const float* __restrict__ bias,
                                 float* __restrict__ aOut, float* __restrict__ dOut)
{
    const int idx = blockIdx.x;
    const int lev = idx >> 6, b = (idx >> 3) & 7, g = idx & 7;
    const int cbS[5] = {0, 128, 160, 168, 170};
    const int Ls[4] = {16384, 4096, 1024, 256};
    double s = 0.0, ss = 0.0;
    for (int cb = cbS[lev]; cb < cbS[lev + 1]; ++cb) {
        double2 p = part2[(size_t)(b * NGROUP + g) * NCB + cb];
        s += p.x; ss += p.y;
    }
    const double cnt = 32.0 * (double)Ls[lev];
    const double mu = s / cnt;
    const float var = (float)(ss / cnt - mu * mu);
    const float rinv = rsqrtf(var + GNEPS);
    const int c = g * 32 + threadIdx.x;
    const float a = scale[c] * rinv;
    aOut[(lev * NBATCH + b) * CFEAT + c] = a;
    dOut[(lev * NBATCH + b) * CFEAT + c] = bias[c] - (float)mu * a;
}

// ---------------- logits ----------------
__global__ __launch_bounds__(256)
void logits_kernel(const float* __restrict__ h, const float* __restrict__ a2,
                   const float* __restrict__ d2, const float* __restrict__ W2,
                   const float* __restrict__ b2, float* __restrict__ logits,
                   float* __restrict__ outLog, int colOff, int L)
{
    __shared__ float sa[256], sd[256], sw[256];
    const int tid = threadIdx.x;
    const int b = blockIdx.y;
    sa[tid] = a2[b * 256 + tid];
    sd[tid] = d2[b * 256 + tid];
    sw[tid] = W2[tid];
    __syncthreads();

    const int rel = blockIdx.x * 1024 + tid * 4;
    if (rel >= L) return;
    const int pos = colOff + rel;
    const float* hp = h + (size_t)b * 256 * NTOT + pos;
    const float bb = b2[0];
    float4 acc = make_float4(bb, bb, bb, bb);
#pragma unroll 4
    for (int c = 0; c < 256; ++c) {
        float4 v = *(const float4*)&hp[(size_t)c * NTOT];
        const float w = sw[c], a = sa[c], d = sd[c];
        acc.x = fmaf(w, fmaxf(fmaf(a, v.x, d), 0.f), acc.x);
        acc.y = fmaf(w, fmaxf(fmaf(a, v.y, d), 0.f), acc.y);
        acc.z = fmaf(w, fmaxf(fmaf(a, v.z, d), 0.f), acc.z);
        acc.w = fmaf(w, fmaxf(fmaf(a, v.w, d), 0.f), acc.w);
    }
    *(float4*)&logits[b * NTOT + pos] = acc;
    if (outLog) *(float4*)&outLog[b * NTOT + pos] = acc;
}

// ---------------- segmented top-100 ----------------
__device__ __forceinline__ unsigned ford(float f) {
    unsigned u = __float_as_uint(f);
    return (u & 0x80000000u) ? ~u : (u | 0x80000000u);
}

__global__ __launch_bounds__(1024)
void topk_kernel(const float* __restrict__ logits, float* __restrict__ outF, int* __restrict__ outI)
{
    extern __shared__ float sv[];
    float* segMax = sv + NTOT;
    __shared__ unsigned long long warpRes[32];
    __shared__ int winSeg;
    const int b = blockIdx.x, tid = threadIdx.x;
    const int lane = tid & 31, wid = tid >> 5;
    const float NEGINF = __int_as_float(0xff800000);

    for (int i = tid; i < NTOT; i += 1024) sv[i] = logits[b * NTOT + i];
    __syncthreads();
    if (tid < NSEG) {
        float m = NEGINF;
        for (int j = 0; j < 32; ++j) m = fmaxf(m, sv[tid * 32 + j]);
        segMax[tid] = m;
    }
    __syncthreads();

    for (int k = 0; k < KTOP; ++k) {
        unsigned long long key = 0ull;
        if (tid < NSEG)
            key = ((unsigned long long)ford(segMax[tid]) << 32) | (unsigned)(NSEG - 1 - tid);
#pragma unroll
        for (int off = 16; off; off >>= 1) {
            unsigned long long o = __shfl_down_sync(0xffffffffu, key, off);
            key = (o > key) ? o : key;
        }
        if (lane == 0) warpRes[wid] = key;
        __syncthreads();
        if (wid == 0) {
            unsigned long long v = warpRes[lane];
#pragma unroll
            for (int off = 16; off; off >>= 1) {
                unsigned long long o = __shfl_down_sync(0xffffffffu, v, off);
                v = (o > v) ? o : v;
            }
            if (lane == 0) winSeg = NSEG - 1 - (int)(v & 0xffffffffu);
        }
        __syncthreads();
        if (wid == 0) {
            const int s = winSeg;
            float v = sv[s * 32 + lane];
            unsigned long long r = ((unsigned long long)ford(v) << 32) | (unsigned)(31 - lane);
#pragma unroll
            for (int off = 16; off; off >>= 1) {
                unsigned long long o = __shfl_xor_sync(0xffffffffu, r, off);
                r = (o > r) ? o : r;
            }
            const int wl = 31 - (int)(r & 31u);
            if (lane == wl) {
                const int idx = s * 32 + wl;
                if (outF) outF[b * KTOP + k] = (float)idx;
                if (outI) outI[b * KTOP + k] = idx;
                sv[idx] = NEGINF;
                v = NEGINF;
            }
            float m = v;
#pragma unroll
            for (int off = 16; off; off >>= 1)
                m = fmaxf(m, __shfl_xor_sync(0xffffffffu, m, off));
            if (lane == 0) segMax[s] = m;
        }
        __syncthreads();
    }
}

// ---------------- host launcher ----------------
extern "C" void kernel_launch(void* const* d_in, const int* in_sizes, int n_in,
                              void* d_out, int out_size)
{
    (void)in_sizes; (void)n_in;
    const float* xs[4] = {(const float*)d_in[0], (const float*)d_in[1],
                          (const float*)d_in[2], (const float*)d_in[3]};
    const float* gn1_scale = (const float*)d_in[4];
    const float* gn1_bias  = (const float*)d_in[5];
    const float* W1        = (const float*)d_in[6];
    const float* b1        = (const float*)d_in[7];
    const float* gn2_scale = (const float*)d_in[8];
    const float* gn2_bias  = (const float*)d_in[9];
    const float* W2        = (const float*)d_in[10];
    const float* b2        = (const float*)d_in[11];

    const int Ls[4]   = {16384, 4096, 1024, 256};
    const int offs[4] = {0, 16384, 20480, 21504};

    void* tmp;
    cudaGetSymbolAddress(&tmp, g_h);      float*   p_h     = (float*)tmp;
    cudaGetSymbolAddress(&tmp, g_logits); float*   p_log   = (float*)tmp;
    cudaGetSymbolAddress(&tmp, g_part1);  double2* p_part1 = (double2*)tmp;
    cudaGetSymbolAddress(&tmp, g_part2);  double2* p_part2 = (double2*)tmp;
    cudaGetSymbolAddress(&tmp, g_a1);     float*   p_a1    = (float*)tmp;
    cudaGetSymbolAddress(&tmp, g_d1);     float*   p_d1    = (float*)tmp;
    cudaGetSymbolAddress(&tmp, g_a2);     float*   p_a2    = (float*)tmp;
    cudaGetSymbolAddress(&tmp, g_d2);     float*   p_d2    = (float*)tmp;

    float* outF   = (float*)d_out;
    float* outLog = nullptr;
    float* outIdF = nullptr;
    int*   outIdI = nullptr;
    const int NIDS = NBATCH * KTOP;
    const int NLOG = NBATCH * NTOT;
    if (out_size >= NIDS + NLOG)      { outIdF = outF; outLog = outF + NIDS; }
    else if (out_size == NLOG)        { outLog = outF; }
    else if (out_size == NIDS)        { outIdI = (int*)d_out; }
    else                              { outIdF = outF; if (out_size > NIDS) outLog = outF + NIDS; }

    stats_all_kernel<<<768, 256>>>(xs[0], xs[1], xs[2], xs[3], p_part1);
    finalize1_kernel<<<4 * NBATCH * NGROUP, 32>>>(p_part1, gn1_scale, gn1_bias, p_a1, p_d1);

    for (int lev = 0; lev < 4; ++lev) {
        gemm_mma_kernel<<<dim3(Ls[lev] / 128, 2, NBATCH), 256>>>(
            xs[lev], W1, b1, p_a1 + lev * NBATCH * CFEAT, p_d1 + lev * NBATCH * CFEAT,
            p_h, p_part2, Ls[lev], offs[lev], offs[lev] / 128);
    }

    finalize2_kernel<<<4 * NBATCH * NGROUP, 32>>>(p_part2, gn2_scale, gn2_bias, p_a2, p_d2);

    for (int lev = 0; lev < 4; ++lev) {
        const int nblk = (Ls[lev] + 1023) / 1024;
        logits_kernel<<<dim3(nblk, NBATCH), 256>>>(
            p_h, p_a2 + lev * NBATCH * CFEAT, p_d2 + lev * NBATCH * CFEAT,
            W2, b2, p_log, outLog, offs[lev], Ls[lev]);
    }

    const int tkSmem = (NTOT + NSEG) * 4;
    cudaFuncSetAttribute(topk_kernel, cudaFuncAttributeMaxDynamicSharedMemorySize, tkSmem);
    topk_kernel<<<NBATCH, 1024, tkSmem>>>(p_log, outIdF, outIdI);
}

// round 9
// speedup vs baseline: 1.2752x; 1.1073x over previous
#include <cuda_runtime.h>
#include <cuda_fp16.h>
#include <cstdint>
#include <cstddef>

#define NBATCH 8
#define CFEAT  256
#define NGROUP 8
#define NTOT   21760
#define KTOP   100
#define GNEPS  1e-5f
#define NCB    170
#define NSEG   680

__device__ float   g_h[(size_t)NBATCH * CFEAT * NTOT];
__device__ float   g_logits[NBATCH * NTOT];
__device__ double2 g_part1[4 * NBATCH * NGROUP * 8];
__device__ double2 g_part2[NBATCH * NGROUP * NCB];
__device__ float   g_a1[4 * NBATCH * CFEAT];
__device__ float   g_d1[4 * NBATCH * CFEAT];
__device__ float   g_a2[4 * NBATCH * CFEAT];
__device__ float   g_d2[4 * NBATCH * CFEAT];
__device__ uint2   g_bsplit[(size_t)NBATCH * NTOT * 128];   // [b][px][kpair] (s1pair, s2pair)
__device__ uint2   g_asplit[256 * 128];                     // [o][kpair]

__device__ __forceinline__ uint32_t pack_h2(float x, float y) {
    __half2 p = __halves2half2(__float2half_rn(x), __float2half_rn(y));
    return *reinterpret_cast<uint32_t*>(&p);
}
// split two adjacent-k fp32 values into (stream1 pair, stream2 pair)
__device__ __forceinline__ uint2 split2(float v0, float v1) {
    float h0 = __half2float(__float2half_rn(v0));
    float h1 = __half2float(__float2half_rn(v1));
    uint2 r;
    r.x = pack_h2(h0, h1);
    r.y = pack_h2(v0 - h0, v1 - h1);
    return r;
}
__device__ __forceinline__ void mma_f16(float* d, uint32_t a0, uint32_t a1, uint32_t a2,
                                        uint32_t a3, uint32_t b0, uint32_t b1) {
    asm volatile(
        "mma.sync.aligned.m16n8k16.row.col.f32.f16.f16.f32 "
        "{%0,%1,%2,%3}, {%4,%5,%6,%7}, {%8,%9}, {%0,%1,%2,%3};"
        : "+f"(d[0]), "+f"(d[1]), "+f"(d[2]), "+f"(d[3])
        : "r"(a0), "r"(a1), "r"(a2), "r"(a3), "r"(b0), "r"(b1));
}

// ---------------- GN1 stats (merged) ----------------
__global__ __launch_bounds__(256)
void stats_all_kernel(const float* __restrict__ x0, const float* __restrict__ x1,
                      const float* __restrict__ x2, const float* __restrict__ x3,
                      double2* __restrict__ part1)
{
    int bi = blockIdx.x;
    int lev, nchLog, L;
    const float* src;
    if (bi < 512)      { lev = 0; nchLog = 3; L = 16384; src = x0; }
    else if (bi < 640) { lev = 1; nchLog = 1; L = 4096;  src = x1; bi -= 512; }
    else if (bi < 704) { lev = 2; nchLog = 0; L = 1024;  src = x2; bi -= 640; }
    else               { lev = 3; nchLog = 0; L = 256;   src = x3; bi -= 704; }
    const int nch = 1 << nchLog;
    const int ch = bi & (nch - 1);
    const int bg = bi >> nchLog;
    const int b = bg >> 3, g = bg & 7;
    const int chunk = L >> nchLog;
    const int q0 = (ch * chunk) >> 2, q1 = ((ch + 1) * chunk) >> 2;
    const int tid = threadIdx.x;

    float s = 0.f, q = 0.f;
    for (int c = 0; c < 32; ++c) {
        const float4* row = (const float4*)(src + (size_t)(b * CFEAT + g * 32 + c) * L);
        for (int i = q0 + tid; i < q1; i += 256) {
            float4 v = row[i];
            s += (v.x + v.y) + (v.z + v.w);
            q += (v.x * v.x + v.y * v.y) + (v.z * v.z + v.w * v.w);
        }
    }
#pragma unroll
    for (int off = 16; off; off >>= 1) {
        s += __shfl_down_sync(0xffffffffu, s, off);
        q += __shfl_down_sync(0xffffffffu, q, off);
    }
    __shared__ float ws[8], wq[8];
    if ((tid & 31) == 0) { ws[tid >> 5] = s; wq[tid >> 5] = q; }
    __syncthreads();
    if (tid == 0) {
        double S = 0.0, Q = 0.0;
        for (int w = 0; w < 8; ++w) { S += (double)ws[w]; Q += (double)wq[w]; }
        part1[lev * 512 + (b * NGROUP + g) * 8 + ch] = make_double2(S, Q);
    }
}

__global__ void finalize1_kernel(const double2* __restrict__ part,
                                 const float* __restrict__ scale, const float* __restrict__ bias,
                                 float* __restrict__ aOut, float* __restrict__ dOut)
{
    const int idx = blockIdx.x;
    const int lev = idx >> 6, b = (idx >> 3) & 7, g = idx & 7;
    const int nchs[4] = {8, 2, 1, 1};
    const int Ls[4] = {16384, 4096, 1024, 256};
    double s = 0.0, ss = 0.0;
    for (int ch = 0; ch < nchs[lev]; ++ch) {
        double2 p = part[lev * 512 + (b * NGROUP + g) * 8 + ch];
        s += p.x; ss += p.y;
    }
    const double cnt = 32.0 * (double)Ls[lev];
    const double mu = s / cnt;
    const float var = (float)(ss / cnt - mu * mu);
    const float rinv = rsqrtf(var + GNEPS);
    const int c = g * 32 + threadIdx.x;
    const float a = scale[c] * rinv;
    aOut[(lev * NBATCH + b) * CFEAT + c] = a;
    dOut[(lev * NBATCH + b) * CFEAT + c] = bias[c] - (float)mu * a;
}

// ---------------- precompute W1 split: [o][kpair] ----------------
__global__ __launch_bounds__(256)
void asplit_kernel(const float* __restrict__ W1, uint2* __restrict__ ag)
{
    const int idx = blockIdx.x * 256 + threadIdx.x;     // o*128 + cp
    const int o = idx >> 7, cp = idx & 127;
    float w0 = W1[o * 256 + cp * 2];
    float w1 = W1[o * 256 + cp * 2 + 1];
    ag[idx] = split2(w0, w1);
}

// ---------------- precompute B split: relu(GN1(x)) -> [b][px][kpair], transposed ----------------
__global__ __launch_bounds__(256)
void bsplit_kernel(const float* __restrict__ x0, const float* __restrict__ x1,
                   const float* __restrict__ x2, const float* __restrict__ x3,
                   const float* __restrict__ a1, const float* __restrict__ d1,
                   uint2* __restrict__ bgout)
{
    __shared__ float v[32][65];
    __shared__ float sa[256], sd[256];
    const int tid = threadIdx.x;
    const int b = blockIdx.y;
    const int px0 = blockIdx.x * 64;                    // global px, tile of 64
    int lev, L, loff;
    const float* xs;
    if (px0 < 16384)      { lev = 0; L = 16384; loff = 0;     xs = x0; }
    else if (px0 < 20480) { lev = 1; L = 4096;  loff = 16384; xs = x1; }
    else if (px0 < 21504) { lev = 2; L = 1024;  loff = 20480; xs = x2; }
    else                  { lev = 3; L = 256;   loff = 21504; xs = x3; }
    const int pxl = px0 - loff;

    sa[tid] = a1[(lev * NBATCH + b) * CFEAT + tid];
    sd[tid] = d1[(lev * NBATCH + b) * CFEAT + tid];
    __syncthreads();

    uint2* outBase = bgout + ((size_t)b * NTOT + px0) * 128;

    for (int cb = 0; cb < 8; ++cb) {
        const int chL = tid >> 3;                       // 0..31
        const int ch = cb * 32 + chL;
        const int pxq = (tid & 7) * 8;
        const float* row = xs + ((size_t)b * CFEAT + ch) * L + pxl + pxq;
        float4 u0 = *(const float4*)row;
        float4 u1 = *(const float4*)(row + 4);
        const float a = sa[ch], d = sd[ch];
        v[chL][pxq + 0] = fmaxf(fmaf(a, u0.x, d), 0.f);
        v[chL][pxq + 1] = fmaxf(fmaf(a, u0.y, d), 0.f);
        v[chL][pxq + 2] = fmaxf(fmaf(a, u0.z, d), 0.f);
        v[chL][pxq + 3] = fmaxf(fmaf(a, u0.w, d), 0.f);
        v[chL][pxq + 4] = fmaxf(fmaf(a, u1.x, d), 0.f);
        v[chL][pxq + 5] = fmaxf(fmaf(a, u1.y, d), 0.f);
        v[chL][pxq + 6] = fmaxf(fmaf(a, u1.z, d), 0.f);
        v[chL][pxq + 7] = fmaxf(fmaf(a, u1.w, d), 0.f);
        __syncthreads();
#pragma unroll
        for (int it = 0; it < 4; ++it) {
            const int idx = it * 256 + tid;
            const int px = idx >> 4, cp = idx & 15;     // cp within ch-block
            uint2 r = split2(v[cp * 2][px], v[cp * 2 + 1][px]);
            outBase[(size_t)px * 128 + cb * 16 + cp] = r;
        }
        __syncthreads();
    }
}

// ---------------- fp16x3 tensor GEMM: copies + mma only; bias + GN2 stats fused out ----------------
__global__ __launch_bounds__(256, 2)
void gemm_f16_kernel(const uint2* __restrict__ ag, const uint2* __restrict__ bg,
                     const float* __restrict__ b1, float* __restrict__ hbase,
                     double2* __restrict__ part2)
{
    __shared__ uint2 As[2][128][10];    // 80B-padded rows: [m][kpair]
    __shared__ uint2 Bs[2][128][10];    // [n(px)][kpair]
    __shared__ float redS[8], redQ[8];

    const int tid = threadIdx.x, wid = tid >> 5, lane = tid & 31;
    const int colTile = blockIdx.x, om2 = blockIdx.y, b = blockIdx.z;
    const int om = om2 * 128;
    const int wm = (wid & 3) * 32, wn = (wid >> 2) * 64;
    const int g = lane >> 2, c = lane & 3;
    const int r = tid >> 1, hf = tid & 1;

    const uint2* aRow = ag + (size_t)(om + r) * 128;
    const uint2* bRow = bg + ((size_t)b * NTOT + colTile * 128 + r) * 128;

    float acc[2][8][4];
#pragma unroll
    for (int i = 0; i < 2; ++i)
#pragma unroll
        for (int j = 0; j < 8; ++j)
#pragma unroll
            for (int t = 0; t < 4; ++t) acc[i][j][t] = 0.f;

    // preload chunk 0
    {
        uint4 pa0 = *(const uint4*)(aRow + hf * 4);
        uint4 pa1 = *(const uint4*)(aRow + hf * 4 + 2);
        uint4 pb0 = *(const uint4*)(bRow + hf * 4);
        uint4 pb1 = *(const uint4*)(bRow + hf * 4 + 2);
        *(uint4*)&As[0][r][hf * 4] = pa0;
        *(uint4*)&As[0][r][hf * 4 + 2] = pa1;
        *(uint4*)&Bs[0][r][hf * 4] = pb0;
        *(uint4*)&Bs[0][r][hf * 4 + 2] = pb1;
    }
    __syncthreads();

    for (int chunk = 0; chunk < 16; ++chunk) {
        const int cur = chunk & 1;
        uint4 na0, na1, nb0, nb1;
        if (chunk < 15) {
            const int off = (chunk + 1) * 8 + hf * 4;
            na0 = *(const uint4*)(aRow + off);
            na1 = *(const uint4*)(aRow + off + 2);
            nb0 = *(const uint4*)(bRow + off);
            nb1 = *(const uint4*)(bRow + off + 2);
        }
        uint2 qa[2][4];
#pragma unroll
        for (int i = 0; i < 2; ++i) {
            const int m = wm + i * 16;
            qa[i][0] = As[cur][m + g][c];
            qa[i][1] = As[cur][m + g + 8][c];
            qa[i][2] = As[cur][m + g][c + 4];
            qa[i][3] = As[cur][m + g + 8][c + 4];
        }
#pragma unroll
        for (int j = 0; j < 8; ++j) {
            const int n = wn + j * 8 + g;
            const uint2 qb0 = Bs[cur][n][c];
            const uint2 qb1 = Bs[cur][n][c + 4];
#pragma unroll
            for (int i = 0; i < 2; ++i) {
                mma_f16(acc[i][j], qa[i][0].x, qa[i][1].x, qa[i][2].x, qa[i][3].x, qb0.x, qb1.x);
                mma_f16(acc[i][j], qa[i][0].y, qa[i][1].y, qa[i][2].y, qa[i][3].y, qb0.x, qb1.x);
                mma_f16(acc[i][j], qa[i][0].x, qa[i][1].x, qa[i][2].x, qa[i][3].x, qb0.y, qb1.y);
            }
        }
        if (chunk < 15) {
            const int nxt = cur ^ 1;
            *(uint4*)&As[nxt][r][hf * 4] = na0;
            *(uint4*)&As[nxt][r][hf * 4 + 2] = na1;
            *(uint4*)&Bs[nxt][r][hf * 4] = nb0;
            *(uint4*)&Bs[nxt][r][hf * 4 + 2] = nb1;
        }
        __syncthreads();
    }

    // epilogue: +bias, write h, fused GN2 partial stats
    float s = 0.f, q = 0.f;
    const int pxBase = colTile * 128;
#pragma unroll
    for (int i = 0; i < 2; ++i) {
        const int r0 = om + wm + i * 16 + g;
        const int r1 = r0 + 8;
        const float bb0 = b1[r0], bb1 = b1[r1];
        float* h0 = hbase + (size_t)(b * 256 + r0) * NTOT + pxBase;
        float* h1 = hbase + (size_t)(b * 256 + r1) * NTOT + pxBase;
#pragma unroll
        for (int j = 0; j < 8; ++j) {
            const int cn = wn + j * 8 + 2 * c;
            float v0 = acc[i][j][0] + bb0, v1 = acc[i][j][1] + bb0;
            float v2 = acc[i][j][2] + bb1, v3 = acc[i][j][3] + bb1;
            *(float2*)&h0[cn] = make_float2(v0, v1);
            *(float2*)&h1[cn] = make_float2(v2, v3);
            s += (v0 + v1) + (v2 + v3);
            q += v0 * v0 + v1 * v1 + v2 * v2 + v3 * v3;
        }
    }
#pragma unroll
    for (int off = 16; off; off >>= 1) {
        s += __shfl_down_sync(0xffffffffu, s, off);
        q += __shfl_down_sync(0xffffffffu, q, off);
    }
    if (lane == 0) { redS[wid] = s; redQ[wid] = q; }
    __syncthreads();
    if (tid < 4) {
        const int grp = om2 * 4 + tid;
        const double S = (double)redS[tid] + (double)redS[tid + 4];
        const double Q = (double)redQ[tid] + (double)redQ[tid + 4];
        part2[(size_t)(b * NGROUP + grp) * NCB + colTile] = make_double2(S, Q);
    }
}

// ---------------- finalize GN2 ----------------
__global__ void finalize2_kernel(const double2* __restrict__ part2,
                                 const float* __restrict__ scale, const float* __restrict__ bias,
                                 float* __restrict__ aOut, float* __restrict__ dOut)
{
    const int idx = blockIdx.x;
    const int lev = idx >> 6, b = (idx >> 3) & 7, g = idx & 7;
    const int cbS[5] = {0, 128, 160, 168, 170};
    const int Ls[4] = {16384, 4096, 1024, 256};
    double s = 0.0, ss = 0.0;
    for (int cb = cbS[lev]; cb < cbS[lev + 1]; ++cb) {
        double2 p = part2[(size_t)(b * NGROUP + g) * NCB + cb];
        s += p.x; ss += p.y;
    }
    const double cnt = 32.0 * (double)Ls[lev];
    const double mu = s / cnt;
    const float var = (float)(ss / cnt - mu * mu);
    const float rinv = rsqrtf(var + GNEPS);
    const int c = g * 32 + threadIdx.x;
    const float a = scale[c] * rinv;
    aOut[(lev * NBATCH + b) * CFEAT + c] = a;
    dOut[(lev * NBATCH + b) * CFEAT + c] = bias[c] - (float)mu * a;
}

// ---------------- logits ----------------
__global__ __launch_bounds__(256)
void logits_kernel(const float* __restrict__ h, const float* __restrict__ a2,
                   const float* __restrict__ d2, const float* __restrict__ W2,
                   const float* __restrict__ b2, float* __restrict__ logits,
                   float* __restrict__ outLog, int colOff, int L)
{
    __shared__ float sa[256], sd[256], sw[256];
    const int tid = threadIdx.x;
    const int b = blockIdx.y;
    sa[tid] = a2[b * 256 + tid];
    sd[tid] = d2[b * 256 + tid];
    sw[tid] = W2[tid];
    __syncthreads();

    const int rel = blockIdx.x * 1024 + tid * 4;
    if (rel >= L) return;
    const int pos = colOff + rel;
    const float* hp = h + (size_t)b * 256 * NTOT + pos;
    const float bb = b2[0];
    float4 acc = make_float4(bb, bb, bb, bb);
#pragma unroll 4
    for (int c = 0; c < 256; ++c) {
        float4 v = *(const float4*)&hp[(size_t)c * NTOT];
        const float w = sw[c], a = sa[c], d = sd[c];
        acc.x = fmaf(w, fmaxf(fmaf(a, v.x, d), 0.f), acc.x);
        acc.y = fmaf(w, fmaxf(fmaf(a, v.y, d), 0.f), acc.y);
        acc.z = fmaf(w, fmaxf(fmaf(a, v.z, d), 0.f), acc.z);
        acc.w = fmaf(w, fmaxf(fmaf(a, v.w, d), 0.f), acc.w);
    }
    *(float4*)&logits[b * NTOT + pos] = acc;
    if (outLog) *(float4*)&outLog[b * NTOT + pos] = acc;
}

// ---------------- segmented top-100 ----------------
__device__ __forceinline__ unsigned ford(float f) {
    unsigned u = __float_as_uint(f);
    return (u & 0x80000000u) ? ~u : (u | 0x80000000u);
}

__global__ __launch_bounds__(1024)
void topk_kernel(const float* __restrict__ logits, float* __restrict__ outF, int* __restrict__ outI)
{
    extern __shared__ float sv[];
    float* segMax = sv + NTOT;
    __shared__ unsigned long long warpRes[32];
    __shared__ int winSeg;
    const int b = blockIdx.x, tid = threadIdx.x;
    const int lane = tid & 31, wid = tid >> 5;
    const float NEGINF = __int_as_float(0xff800000);

    for (int i = tid; i < NTOT; i += 1024) sv[i] = logits[b * NTOT + i];
    __syncthreads();
    if (tid < NSEG) {
        float m = NEGINF;
        for (int j = 0; j < 32; ++j) m = fmaxf(m, sv[tid * 32 + j]);
        segMax[tid] = m;
    }
    __syncthreads();

    for (int k = 0; k < KTOP; ++k) {
        unsigned long long key = 0ull;
        if (tid < NSEG)
            key = ((unsigned long long)ford(segMax[tid]) << 32) | (unsigned)(NSEG - 1 - tid);
#pragma unroll
        for (int off = 16; off; off >>= 1) {
            unsigned long long o = __shfl_down_sync(0xffffffffu, key, off);
            key = (o > key) ? o : key;
        }
        if (lane == 0) warpRes[wid] = key;
        __syncthreads();
        if (wid == 0) {
            unsigned long long v = warpRes[lane];
#pragma unroll
            for (int off = 16; off; off >>= 1) {
                unsigned long long o = __shfl_down_sync(0xffffffffu, v, off);
                v = (o > v) ? o : v;
            }
            if (lane == 0) winSeg = NSEG - 1 - (int)(v & 0xffffffffu);
        }
        __syncthreads();
        if (wid == 0) {
            const int s = winSeg;
            float v = sv[s * 32 + lane];
            unsigned long long r = ((unsigned long long)ford(v) << 32) | (unsigned)(31 - lane);
#pragma unroll
            for (int off = 16; off; off >>= 1) {
                unsigned long long o = __shfl_xor_sync(0xffffffffu, r, off);
                r = (o > r) ? o : r;
            }
            const int wl = 31 - (int)(r & 31u);
            if (lane == wl) {
                const int idx = s * 32 + wl;
                if (outF) outF[b * KTOP + k] = (float)idx;
                if (outI) outI[b * KTOP + k] = idx;
                sv[idx] = NEGINF;
                v = NEGINF;
            }
            float m = v;
#pragma unroll
            for (int off = 16; off; off >>= 1)
                m = fmaxf(m, __shfl_xor_sync(0xffffffffu, m, off));
            if (lane == 0) segMax[s] = m;
        }
        __syncthreads();
    }
}

// ---------------- host launcher ----------------
extern "C" void kernel_launch(void* const* d_in, const int* in_sizes, int n_in,
                              void* d_out, int out_size)
{
    (void)in_sizes; (void)n_in;
    const float* xs[4] = {(const float*)d_in[0], (const float*)d_in[1],
                          (const float*)d_in[2], (const float*)d_in[3]};
    const float* gn1_scale = (const float*)d_in[4];
    const float* gn1_bias  = (const float*)d_in[5];
    const float* W1        = (const float*)d_in[6];
    const float* b1        = (const float*)d_in[7];
    const float* gn2_scale = (const float*)d_in[8];
    const float* gn2_bias  = (const float*)d_in[9];
    const float* W2        = (const float*)d_in[10];
    const float* b2        = (const float*)d_in[11];

    const int Ls[4]   = {16384, 4096, 1024, 256};
    const int offs[4] = {0, 16384, 20480, 21504};

    void* tmp;
    cudaGetSymbolAddress(&tmp, g_h);      float*   p_h    = (float*)tmp;
    cudaGetSymbolAddress(&tmp, g_logits); float*   p_log  = (float*)tmp;
    cudaGetSymbolAddress(&tmp, g_part1);  double2* p_p1   = (double2*)tmp;
    cudaGetSymbolAddress(&tmp, g_part2);  double2* p_p2   = (double2*)tmp;
    cudaGetSymbolAddress(&tmp, g_a1);     float*   p_a1   = (float*)tmp;
    cudaGetSymbolAddress(&tmp, g_d1);     float*   p_d1   = (float*)tmp;
    cudaGetSymbolAddress(&tmp, g_a2);     float*   p_a2   = (float*)tmp;
    cudaGetSymbolAddress(&tmp, g_d2);     float*   p_d2   = (float*)tmp;
    cudaGetSymbolAddress(&tmp, g_bsplit); uint2*   p_bg   = (uint2*)tmp;
    cudaGetSymbolAddress(&tmp, g_asplit); uint2*   p_ag   = (uint2*)tmp;

    float* outF   = (float*)d_out;
    float* outLog = nullptr;
    float* outIdF = nullptr;
    int*   outIdI = nullptr;
    const int NIDS = NBATCH * KTOP;
    const int NLOG = NBATCH * NTOT;
    if (out_size >= NIDS + NLOG)      { outIdF = outF; outLog = outF + NIDS; }
    else if (out_size == NLOG)        { outLog = outF; }
    else if (out_size == NIDS)        { outIdI = (int*)d_out; }
    else                              { outIdF = outF; if (out_size > NIDS) outLog = outF + NIDS; }

    stats_all_kernel<<<768, 256>>>(xs[0], xs[1], xs[2], xs[3], p_p1);
    finalize1_kernel<<<4 * NBATCH * NGROUP, 32>>>(p_p1, gn1_scale, gn1_bias, p_a1, p_d1);

    asplit_kernel<<<128, 256>>>(W1, p_ag);
    bsplit_kernel<<<dim3(NTOT / 64, NBATCH), 256>>>(xs[0], xs[1], xs[2], xs[3], p_a1, p_d1, p_bg);

    gemm_f16_kernel<<<dim3(NCB, 2, NBATCH), 256>>>(p_ag, p_bg, b1, p_h, p_p2);

    finalize2_kernel<<<4 * NBATCH * NGROUP, 32>>>(p_p2, gn2_scale, gn2_bias, p_a2, p_d2);

    for (int lev = 0; lev < 4; ++lev) {
        const int nblk = (Ls[lev] + 1023) / 1024;
        logits_kernel<<<dim3(nblk, NBATCH), 256>>>(
            p_h, p_a2 + lev * NBATCH * CFEAT, p_d2 + lev * NBATCH * CFEAT,
            W2, b2, p_log, outLog, offs[lev], Ls[lev]);
    }

    const int tkSmem = (NTOT + NSEG) * 4;
    cudaFuncSetAttribute(topk_kernel, cudaFuncAttributeMaxDynamicSharedMemorySize, tkSmem);
    topk_kernel<<<NBATCH, 1024, tkSmem>>>(p_log, outIdF, outIdI);
}

// round 11
// speedup vs baseline: 1.3075x; 1.0253x over previous
#include <cuda_runtime.h>
#include <cuda_fp16.h>
#include <cstdint>
#include <cstddef>

#define NBATCH 8
#define CFEAT  256
#define NGROUP 8
#define NTOT   21760
#define KTOP   100
#define GNEPS  1e-5f
#define NCB    170
#define NSEG   680

__device__ float   g_h[(size_t)NBATCH * CFEAT * NTOT];
__device__ float   g_logits[NBATCH * NTOT];
__device__ double2 g_part1[4 * NBATCH * NGROUP * 8];
__device__ double2 g_part2[NBATCH * NGROUP * NCB];
__device__ float   g_a1[4 * NBATCH * CFEAT];
__device__ float   g_d1[4 * NBATCH * CFEAT];
__device__ float   g_a2[4 * NBATCH * CFEAT];
__device__ float   g_d2[4 * NBATCH * CFEAT];
__device__ uint2   g_bsplit[(size_t)NBATCH * NTOT * 128];   // [b][px][kpair-permuted]
__device__ uint2   g_asplit[256 * 128];                     // [o][kpair-permuted]

__device__ __forceinline__ uint32_t pack_h2(float x, float y) {
    __half2 p = __halves2half2(__float2half_rn(x), __float2half_rn(y));
    return *reinterpret_cast<uint32_t*>(&p);
}
__device__ __forceinline__ uint2 split2(float v0, float v1) {
    float h0 = __half2float(__float2half_rn(v0));
    float h1 = __half2float(__float2half_rn(v1));
    uint2 r;
    r.x = pack_h2(h0, h1);
    r.y = pack_h2(v0 - h0, v1 - h1);
    return r;
}
// kpair permutation: within each k16 chunk (8 kpairs), pair (c, c+4) stored adjacently.
__device__ __forceinline__ int kp_perm(int kp) {
    const int chunk = kp >> 3, w = kp & 7;
    return chunk * 8 + (((w & 3) << 1) | (w >> 2));
}
__device__ __forceinline__ void mma_f16(float* d, uint32_t a0, uint32_t a1, uint32_t a2,
                                        uint32_t a3, uint32_t b0, uint32_t b1) {
    asm volatile(
        "mma.sync.aligned.m16n8k16.row.col.f32.f16.f16.f32 "
        "{%0,%1,%2,%3}, {%4,%5,%6,%7}, {%8,%9}, {%0,%1,%2,%3};"
        : "+f"(d[0]), "+f"(d[1]), "+f"(d[2]), "+f"(d[3])
        : "r"(a0), "r"(a1), "r"(a2), "r"(a3), "r"(b0), "r"(b1));
}
__device__ __forceinline__ uint4 lds128(uint32_t a) {
    uint4 r;
    asm volatile("ld.shared.v4.u32 {%0,%1,%2,%3}, [%4];"
                 : "=r"(r.x), "=r"(r.y), "=r"(r.z), "=r"(r.w) : "r"(a));
    return r;
}
#define CP_ASYNC16(dst, src) \
    asm volatile("cp.async.cg.shared.global [%0], [%1], 16;" :: "r"(dst), "l"(src))
#define CP_COMMIT() asm volatile("cp.async.commit_group;" ::: "memory")
#define CP_WAIT1()  asm volatile("cp.async.wait_group 1;" ::: "memory")

// ---------------- GN1 stats (merged) + W1 split tail blocks ----------------
__global__ __launch_bounds__(256)
void stats_all_kernel(const float* __restrict__ x0, const float* __restrict__ x1,
                      const float* __restrict__ x2, const float* __restrict__ x3,
                      double2* __restrict__ part1,
                      const float* __restrict__ W1, uint2* __restrict__ ag)
{
    int bi = blockIdx.x;
    const int tid = threadIdx.x;
    if (bi >= 768) {   // asplit tail: W1 -> fp16 split pairs, permuted
        const int idx = (bi - 768) * 256 + tid;       // o*128 + kp
        const int o = idx >> 7, kp = idx & 127;
        float w0 = W1[o * 256 + kp * 2];
        float w1 = W1[o * 256 + kp * 2 + 1];
        ag[o * 128 + kp_perm(kp)] = split2(w0, w1);
        return;
    }
    int lev, nchLog, L;
    const float* src;
    if (bi < 512)      { lev = 0; nchLog = 3; L = 16384; src = x0; }
    else if (bi < 640) { lev = 1; nchLog = 1; L = 4096;  src = x1; bi -= 512; }
    else if (bi < 704) { lev = 2; nchLog = 0; L = 1024;  src = x2; bi -= 640; }
    else               { lev = 3; nchLog = 0; L = 256;   src = x3; bi -= 704; }
    const int nch = 1 << nchLog;
    const int ch = bi & (nch - 1);
    const int bg = bi >> nchLog;
    const int b = bg >> 3, g = bg & 7;
    const int chunk = L >> nchLog;
    const int q0 = (ch * chunk) >> 2, q1 = ((ch + 1) * chunk) >> 2;

    float s = 0.f, q = 0.f;
    for (int c = 0; c < 32; ++c) {
        const float4* row = (const float4*)(src + (size_t)(b * CFEAT + g * 32 + c) * L);
        for (int i = q0 + tid; i < q1; i += 256) {
            float4 v = row[i];
            s += (v.x + v.y) + (v.z + v.w);
            q += (v.x * v.x + v.y * v.y) + (v.z * v.z + v.w * v.w);
        }
    }
#pragma unroll
    for (int off = 16; off; off >>= 1) {
        s += __shfl_down_sync(0xffffffffu, s, off);
        q += __shfl_down_sync(0xffffffffu, q, off);
    }
    __shared__ float ws[8], wq[8];
    if ((tid & 31) == 0) { ws[tid >> 5] = s; wq[tid >> 5] = q; }
    __syncthreads();
    if (tid == 0) {
        double S = 0.0, Q = 0.0;
        for (int w = 0; w < 8; ++w) { S += (double)ws[w]; Q += (double)wq[w]; }
        part1[lev * 512 + (b * NGROUP + g) * 8 + ch] = make_double2(S, Q);
    }
}

__global__ void finalize1_kernel(const double2* __restrict__ part,
                                 const float* __restrict__ scale, const float* __restrict__ bias,
                                 float* __restrict__ aOut, float* __restrict__ dOut)
{
    const int idx = blockIdx.x;
    const int lev = idx >> 6, b = (idx >> 3) & 7, g = idx & 7;
    const int nchs[4] = {8, 2, 1, 1};
    const int Ls[4] = {16384, 4096, 1024, 256};
    double s = 0.0, ss = 0.0;
    for (int ch = 0; ch < nchs[lev]; ++ch) {
        double2 p = part[lev * 512 + (b * NGROUP + g) * 8 + ch];
        s += p.x; ss += p.y;
    }
    const double cnt = 32.0 * (double)Ls[lev];
    const double mu = s / cnt;
    const float var = (float)(ss / cnt - mu * mu);
    const float rinv = rsqrtf(var + GNEPS);
    const int c = g * 32 + threadIdx.x;
    const float a = scale[c] * rinv;
    aOut[(lev * NBATCH + b) * CFEAT + c] = a;
    dOut[(lev * NBATCH + b) * CFEAT + c] = bias[c] - (float)mu * a;
}

// ---------------- B split: relu(GN1(x)) -> [b][px][kpair-permuted] ----------------
__global__ __launch_bounds__(256)
void bsplit_kernel(const float* __restrict__ x0, const float* __restrict__ x1,
                   const float* __restrict__ x2, const float* __restrict__ x3,
                   const float* __restrict__ a1, const float* __restrict__ d1,
                   uint2* __restrict__ bgout)
{
    __shared__ float v[32][65];
    __shared__ float sa[256], sd[256];
    const int tid = threadIdx.x;
    const int b = blockIdx.y;
    const int px0 = blockIdx.x * 64;
    int lev, L, loff;
    const float* xs;
    if (px0 < 16384)      { lev = 0; L = 16384; loff = 0;     xs = x0; }
    else if (px0 < 20480) { lev = 1; L = 4096;  loff = 16384; xs = x1; }
    else if (px0 < 21504) { lev = 2; L = 1024;  loff = 20480; xs = x2; }
    else                  { lev = 3; L = 256;   loff = 21504; xs = x3; }
    const int pxl = px0 - loff;

    sa[tid] = a1[(lev * NBATCH + b) * CFEAT + tid];
    sd[tid] = d1[(lev * NBATCH + b) * CFEAT + tid];
    __syncthreads();

    uint2* outBase = bgout + ((size_t)b * NTOT + px0) * 128;

    for (int cb = 0; cb < 8; ++cb) {
        const int chL = tid >> 3;
        const int ch = cb * 32 + chL;
        const int pxq = (tid & 7) * 8;
        const float* row = xs + ((size_t)b * CFEAT + ch) * L + pxl + pxq;
        float4 u0 = *(const float4*)row;
        float4 u1 = *(const float4*)(row + 4);
        const float a = sa[ch], d = sd[ch];
        v[chL][pxq + 0] = fmaxf(fmaf(a, u0.x, d), 0.f);
        v[chL][pxq + 1] = fmaxf(fmaf(a, u0.y, d), 0.f);
        v[chL][pxq + 2] = fmaxf(fmaf(a, u0.z, d), 0.f);
        v[chL][pxq + 3] = fmaxf(fmaf(a, u0.w, d), 0.f);
        v[chL][pxq + 4] = fmaxf(fmaf(a, u1.x, d), 0.f);
        v[chL][pxq + 5] = fmaxf(fmaf(a, u1.y, d), 0.f);
        v[chL][pxq + 6] = fmaxf(fmaf(a, u1.z, d), 0.f);
        v[chL][pxq + 7] = fmaxf(fmaf(a, u1.w, d), 0.f);
        __syncthreads();
#pragma unroll
        for (int it = 0; it < 4; ++it) {
            const int idx = it * 256 + tid;
            const int px = idx >> 4, cp = idx & 15;
            uint2 r = split2(v[cp * 2][px], v[cp * 2 + 1][px]);
            outBase[(size_t)px * 128 + kp_perm(cb * 16 + cp)] = r;
        }
        __syncthreads();
    }
}

// ---------------- fp16x3 GEMM: cp.async 3-stage + LDS.128 frags; bias + GN2 stats out ----------------
// dynamic smem: 3 stages x (A 8KB + B 8KB) = 48KB. Stage rows are 64B (conflict-free frag loads).
__global__ __launch_bounds__(256, 2)
void gemm_f16_kernel(const uint2* __restrict__ ag, const uint2* __restrict__ bg,
                     const float* __restrict__ b1, float* __restrict__ hbase,
                     double2* __restrict__ part2)
{
    extern __shared__ char dynsmem[];
    __shared__ float redS[8], redQ[8];

    const int tid = threadIdx.x, wid = tid >> 5, lane = tid & 31;
    const int colTile = blockIdx.x, om2 = blockIdx.y, b = blockIdx.z;
    const int om = om2 * 128;
    const int wm = (wid & 3) * 32, wn = (wid >> 2) * 64;
    const int g = lane >> 2, c = lane & 3;

    // staging role: threads 0-127 stage A rows, 128-255 stage B rows
    const bool isB = tid >= 128;
    const int srow = tid & 127;
    const char* srcBase = (const char*)(isB
        ? (bg + ((size_t)b * NTOT + colTile * 128 + srow) * 128)
        : (ag + (size_t)(om + srow) * 128));
    const uint32_t sbase = (uint32_t)__cvta_generic_to_shared(dynsmem);
    const uint32_t dstRow = sbase + (isB ? 8192u : 0u) + (uint32_t)srow * 64u;

    float acc[2][8][4];
#pragma unroll
    for (int i = 0; i < 2; ++i)
#pragma unroll
        for (int j = 0; j < 8; ++j)
#pragma unroll
            for (int t = 0; t < 4; ++t) acc[i][j][t] = 0.f;

    // prologue: stage chunks 0,1
#pragma unroll
    for (int p = 0; p < 2; ++p) {
        const uint32_t d = dstRow + p * 16384u;
        const char* s = srcBase + p * 64;
        CP_ASYNC16(d, s); CP_ASYNC16(d + 16, s + 16);
        CP_ASYNC16(d + 32, s + 32); CP_ASYNC16(d + 48, s + 48);
        CP_COMMIT();
    }

    const uint32_t aFragBase = sbase + (uint32_t)(wm) * 64u;
    const uint32_t bFragBase = sbase + 8192u + (uint32_t)(wn) * 64u;

#pragma unroll 1
    for (int chunk = 0; chunk < 16; ++chunk) {
        const int stage = chunk % 3;
        const uint32_t stOff = (uint32_t)stage * 16384u;
        CP_WAIT1();
        __syncthreads();

        uint4 ua[2][2];
#pragma unroll
        for (int i = 0; i < 2; ++i) {
            ua[i][0] = lds128(aFragBase + stOff + (uint32_t)(i * 16 + g) * 64u + c * 16u);
            ua[i][1] = lds128(aFragBase + stOff + (uint32_t)(i * 16 + g + 8) * 64u + c * 16u);
        }
#pragma unroll
        for (int j = 0; j < 8; ++j) {
            uint4 ub = lds128(bFragBase + stOff + (uint32_t)(j * 8 + g) * 64u + c * 16u);
#pragma unroll
            for (int i = 0; i < 2; ++i) {
                mma_f16(acc[i][j], ua[i][0].x, ua[i][1].x, ua[i][0].z, ua[i][1].z, ub.x, ub.z);
                mma_f16(acc[i][j], ua[i][0].y, ua[i][1].y, ua[i][0].w, ua[i][1].w, ub.x, ub.z);
                mma_f16(acc[i][j], ua[i][0].x, ua[i][1].x, ua[i][0].z, ua[i][1].z, ub.y, ub.w);
            }
        }
        if (chunk + 2 < 16) {
            const int ns = (chunk + 2) % 3;
            const uint32_t d = dstRow + (uint32_t)ns * 16384u;
            const char* s = srcBase + (chunk + 2) * 64;
            CP_ASYNC16(d, s); CP_ASYNC16(d + 16, s + 16);
            CP_ASYNC16(d + 32, s + 32); CP_ASYNC16(d + 48, s + 48);
        }
        CP_COMMIT();
    }

    // epilogue: +bias, write h, fused GN2 partial stats
    float s = 0.f, q = 0.f;
    const int pxBase = colTile * 128;
#pragma unroll
    for (int i = 0; i < 2; ++i) {
        const int r0 = om + wm + i * 16 + g;
        const int r1 = r0 + 8;
        const float bb0 = b1[r0], bb1 = b1[r1];
        float* h0 = hbase + (size_t)(b * 256 + r0) * NTOT + pxBase;
        float* h1 = hbase + (size_t)(b * 256 + r1) * NTOT + pxBase;
#pragma unroll
        for (int j = 0; j < 8; ++j) {
            const int cn = wn + j * 8 + 2 * c;
            float v0 = acc[i][j][0] + bb0, v1 = acc[i][j][1] + bb0;
            float v2 = acc[i][j][2] + bb1, v3 = acc[i][j][3] + bb1;
            *(float2*)&h0[cn] = make_float2(v0, v1);
            *(float2*)&h1[cn] = make_float2(v2, v3);
            s += (v0 + v1) + (v2 + v3);
            q += v0 * v0 + v1 * v1 + v2 * v2 + v3 * v3;
        }
    }
#pragma unroll
    for (int off = 16; off; off >>= 1) {
        s += __shfl_down_sync(0xffffffffu, s, off);
        q += __shfl_down_sync(0xffffffffu, q, off);
    }
    if (lane == 0) { redS[wid] = s; redQ[wid] = q; }
    __syncthreads();
    if (tid < 4) {
        const int grp = om2 * 4 + tid;
        const double S = (double)redS[tid] + (double)redS[tid + 4];
        const double Q = (double)redQ[tid] + (double)redQ[tid + 4];
        part2[(size_t)(b * NGROUP + grp) * NCB + colTile] = make_double2(S, Q);
    }
}

// ---------------- finalize GN2 ----------------
__global__ void finalize2_kernel(const double2* __restrict__ part2,
                                 const float* __restrict__ scale, const float* __restrict__ bias,
                                 float* __restrict__ aOut, float* __restrict__ dOut)
{
    const int idx = blockIdx.x;
    const int lev = idx >> 6, b = (idx >> 3) & 7, g = idx & 7;
    const int cbS[5] = {0, 128, 160, 168, 170};
    const int Ls[4] = {16384, 4096, 1024, 256};
    double s = 0.0, ss = 0.0;
    for (int cb = cbS[lev]; cb < cbS[lev + 1]; ++cb) {
        double2 p = part2[(size_t)(b * NGROUP + g) * NCB + cb];
        s += p.x; ss += p.y;
    }
    const double cnt = 32.0 * (double)Ls[lev];
    const double mu = s / cnt;
    const float var = (float)(ss / cnt - mu * mu);
    const float rinv = rsqrtf(var + GNEPS);
    const int c = g * 32 + threadIdx.x;
    const float a = scale[c] * rinv;
    aOut[(lev * NBATCH + b) * CFEAT + c] = a;
    dOut[(lev * NBATCH + b) * CFEAT + c] = bias[c] - (float)mu * a;
}

// ---------------- logits ----------------
__global__ __launch_bounds__(256)
void logits_kernel(const float* __restrict__ h, const float* __restrict__ a2,
                   const float* __restrict__ d2, const float* __restrict__ W2,
                   const float* __restrict__ b2, float* __restrict__ logits,
                   float* __restrict__ outLog, int colOff, int L)
{
    __shared__ float sa[256], sd[256], sw[256];
    const int tid = threadIdx.x;
    const int b = blockIdx.y;
    sa[tid] = a2[b * 256 + tid];
    sd[tid] = d2[b * 256 + tid];
    sw[tid] = W2[tid];
    __syncthreads();

    const int rel = blockIdx.x * 1024 + tid * 4;
    if (rel >= L) return;
    const int pos = colOff + rel;
    const float* hp = h + (size_t)b * 256 * NTOT + pos;
    const float bb = b2[0];
    float4 acc = make_float4(bb, bb, bb, bb);
#pragma unroll 4
    for (int c = 0; c < 256; ++c) {
        float4 v = *(const float4*)&hp[(size_t)c * NTOT];
        const float w = sw[c], a = sa[c], d = sd[c];
        acc.x = fmaf(w, fmaxf(fmaf(a, v.x, d), 0.f), acc.x);
        acc.y = fmaf(w, fmaxf(fmaf(a, v.y, d), 0.f), acc.y);
        acc.z = fmaf(w, fmaxf(fmaf(a, v.z, d), 0.f), acc.z);
        acc.w = fmaf(w, fmaxf(fmaf(a, v.w, d), 0.f), acc.w);
    }
    *(float4*)&logits[b * NTOT + pos] = acc;
    if (outLog) *(float4*)&outLog[b * NTOT + pos] = acc;
}

// ---------------- segmented top-100 ----------------
__device__ __forceinline__ unsigned ford(float f) {
    unsigned u = __float_as_uint(f);
    return (u & 0x80000000u) ? ~u : (u | 0x80000000u);
}

__global__ __launch_bounds__(1024)
void topk_kernel(const float* __restrict__ logits, float* __restrict__ outF, int* __restrict__ outI)
{
    extern __shared__ float sv[];
    float* segMax = sv + NTOT;
    __shared__ unsigned long long warpRes[32];
    __shared__ int winSeg;
    const int b = blockIdx.x, tid = threadIdx.x;
    const int lane = tid & 31, wid = tid >> 5;
    const float NEGINF = __int_as_float(0xff800000);

    for (int i = tid; i < NTOT; i += 1024) sv[i] = logits[b * NTOT + i];
    __syncthreads();
    if (tid < NSEG) {
        float m = NEGINF;
        for (int j = 0; j < 32; ++j) m = fmaxf(m, sv[tid * 32 + j]);
        segMax[tid] = m;
    }
    __syncthreads();

    for (int k = 0; k < KTOP; ++k) {
        unsigned long long key = 0ull;
        if (tid < NSEG)
            key = ((unsigned long long)ford(segMax[tid]) << 32) | (unsigned)(NSEG - 1 - tid);
#pragma unroll
        for (int off = 16; off; off >>= 1) {
            unsigned long long o = __shfl_down_sync(0xffffffffu, key, off);
            key = (o > key) ? o : key;
        }
        if (lane == 0) warpRes[wid] = key;
        __syncthreads();
        if (wid == 0) {
            unsigned long long v = warpRes[lane];
#pragma unroll
            for (int off = 16; off; off >>= 1) {
                unsigned long long o = __shfl_down_sync(0xffffffffu, v, off);
                v = (o > v) ? o : v;
            }
            if (lane == 0) winSeg = NSEG - 1 - (int)(v & 0xffffffffu);
        }
        __syncthreads();
        if (wid == 0) {
            const int s = winSeg;
            float v = sv[s * 32 + lane];
            unsigned long long r = ((unsigned long long)ford(v) << 32) | (unsigned)(31 - lane);
#pragma unroll
            for (int off = 16; off; off >>= 1) {
                unsigned long long o = __shfl_xor_sync(0xffffffffu, r, off);
                r = (o > r) ? o : r;
            }
            const int wl = 31 - (int)(r & 31u);
            if (lane == wl) {
                const int idx = s * 32 + wl;
                if (outF) outF[b * KTOP + k] = (float)idx;
                if (outI) outI[b * KTOP + k] = idx;
                sv[idx] = NEGINF;
                v = NEGINF;
            }
            float m = v;
#pragma unroll
            for (int off = 16; off; off >>= 1)
                m = fmaxf(m, __shfl_xor_sync(0xffffffffu, m, off));
            if (lane == 0) segMax[s] = m;
        }
        __syncthreads();
    }
}

// ---------------- host launcher ----------------
extern "C" void kernel_launch(void* const* d_in, const int* in_sizes, int n_in,
                              void* d_out, int out_size)
{
    (void)in_sizes; (void)n_in;
    const float* xs[4] = {(const float*)d_in[0], (const float*)d_in[1],
                          (const float*)d_in[2], (const float*)d_in[3]};
    const float* gn1_scale = (const float*)d_in[4];
    const float* gn1_bias  = (const float*)d_in[5];
    const float* W1        = (const float*)d_in[6];
    const float* b1        = (const float*)d_in[7];
    const float* gn2_scale = (const float*)d_in[8];
    const float* gn2_bias  = (const float*)d_in[9];
    const float* W2        = (const float*)d_in[10];
    const float* b2        = (const float*)d_in[11];

    const int Ls[4]   = {16384, 4096, 1024, 256};
    const int offs[4] = {0, 16384, 20480, 21504};

    void* tmp;
    cudaGetSymbolAddress(&tmp, g_h);      float*   p_h    = (float*)tmp;
    cudaGetSymbolAddress(&tmp, g_logits); float*   p_log  = (float*)tmp;
    cudaGetSymbolAddress(&tmp, g_part1);  double2* p_p1   = (double2*)tmp;
    cudaGetSymbolAddress(&tmp, g_part2);  double2* p_p2   = (double2*)tmp;
    cudaGetSymbolAddress(&tmp, g_a1);     float*   p_a1   = (float*)tmp;
    cudaGetSymbolAddress(&tmp, g_d1);     float*   p_d1   = (float*)tmp;
    cudaGetSymbolAddress(&tmp, g_a2);     float*   p_a2   = (float*)tmp;
    cudaGetSymbolAddress(&tmp, g_d2);     float*   p_d2   = (float*)tmp;
    cudaGetSymbolAddress(&tmp, g_bsplit); uint2*   p_bg   = (uint2*)tmp;
    cudaGetSymbolAddress(&tmp, g_asplit); uint2*   p_ag   = (uint2*)tmp;

    float* outF   = (float*)d_out;
    float* outLog = nullptr;
    float* outIdF = nullptr;
    int*   outIdI = nullptr;
    const int NIDS = NBATCH * KTOP;
    const int NLOG = NBATCH * NTOT;
    if (out_size >= NIDS + NLOG)      { outIdF = outF; outLog = outF + NIDS; }
    else if (out_size == NLOG)        { outLog = outF; }
    else if (out_size == NIDS)        { outIdI = (int*)d_out; }
    else                              { outIdF = outF; if (out_size > NIDS) outLog = outF + NIDS; }

    // launch 1: GN1 stats + W1 split tail
    stats_all_kernel<<<896, 256>>>(xs[0], xs[1], xs[2], xs[3], p_p1, W1, p_ag);
    // launch 2
    finalize1_kernel<<<4 * NBATCH * NGROUP, 32>>>(p_p1, gn1_scale, gn1_bias, p_a1, p_d1);
    // launch 3
    bsplit_kernel<<<dim3(NTOT / 64, NBATCH), 256>>>(xs[0], xs[1], xs[2], xs[3], p_a1, p_d1, p_bg);
    // launch 4 (profiled): GEMM
    cudaFuncSetAttribute(gemm_f16_kernel, cudaFuncAttributeMaxDynamicSharedMemorySize, 49152);
    gemm_f16_kernel<<<dim3(NCB, 2, NBATCH), 256, 49152>>>(p_ag, p_bg, b1, p_h, p_p2);

    finalize2_kernel<<<4 * NBATCH * NGROUP, 32>>>(p_p2, gn2_scale, gn2_bias, p_a2, p_d2);

    for (int lev = 0; lev < 4; ++lev) {
        const int nblk = (Ls[lev] + 1023) / 1024;
        logits_kernel<<<dim3(nblk, NBATCH), 256>>>(
            p_h, p_a2 + lev * NBATCH * CFEAT, p_d2 + lev * NBATCH * CFEAT,
            W2, b2, p_log, outLog, offs[lev], Ls[lev]);
    }

    const int tkSmem = (NTOT + NSEG) * 4;
    cudaFuncSetAttribute(topk_kernel, cudaFuncAttributeMaxDynamicSharedMemorySize, tkSmem);
    topk_kernel<<<NBATCH, 1024, tkSmem>>>(p_log, outIdF, outIdI);
}